// round 4
// baseline (speedup 1.0000x reference)
#include <cuda_runtime.h>

// QNNClassifier: 14-qubit statevector, BATCH=2048, DEPTH=8.
// One CTA per batch element; state in shared memory as SoA (sRe/sIm, 128 KB).
// CX gates deferred as GF(2) relabeling; 112 fused RZ+RY gates applied 4 per
// pass over 16-amplitude cosets held in registers. NEW in this round: the two
// cosets each thread owns are processed in the two lanes of packed f32x2
// arithmetic (fma.rn.f32x2 / mul.rn.f32x2 -> SASS FFMA2/FMUL2), halving the
// fma-pipe instruction count, which R2 profiling showed to be the floor.

#define NQ       14
#define QDIM     16384
#define DEPTH    8
#define NGATES   (DEPTH * NQ)     // 112
#define NPASS    (NGATES / 4)     // 28
#define NTHREADS 512

typedef unsigned long long u64;

struct Consts {
    int   piv[NPASS][4];          // sorted pivot bits (coset rep enumeration)
    int   M[NPASS][4];            // the 4 flip masks (v) per pass
    int   F[NPASS][4];            // parity masks per gate
    int   lut[NPASS][4];          // 16-bit LUT: parity(F & V[t]) per t
    float trig[NPASS][4][4];      // cz, sz, cy, sy per gate
    int   ffin;                   // final measurement parity mask
};
__device__ Consts dC;

// ---------------- setup kernel ----------------
__global__ void qnn_setup(const float* __restrict__ params)
{
    __shared__ int vg[NGATES], fg[NGATES];
    const int tid = threadIdx.x;

    if (tid == 0) {
        int v[NQ], f[NQ];
        #pragma unroll
        for (int q = 0; q < NQ; ++q) { v[q] = 1 << (NQ - 1 - q); f[q] = v[q]; }
        for (int l = 0; l < DEPTH; ++l) {
            for (int q = 0; q < NQ; ++q) { fg[l * NQ + q] = f[q]; vg[l * NQ + q] = v[q]; }
            for (int c = 0; c < NQ; ++c) {          // CX ring after the layer
                int t = (c + 1) % NQ;
                v[c] ^= v[t];
                f[t] ^= f[c];
            }
        }
        dC.ffin = f[0];
    }
    __syncthreads();

    if (tid < NGATES) {
        float tz = params[2 * tid];
        float ty = params[2 * tid + 1];
        float sz, cz, sy, cy;
        sincosf(0.5f * tz, &sz, &cz);
        sincosf(0.5f * ty, &sy, &cy);
        int p = tid >> 2, i = tid & 3;
        dC.trig[p][i][0] = cz; dC.trig[p][i][1] = sz;
        dC.trig[p][i][2] = cy; dC.trig[p][i][3] = sy;
        dC.F[p][i] = fg[tid];
    }

    if (tid < NPASS) {
        int m[4];
        #pragma unroll
        for (int i = 0; i < 4; ++i) { m[i] = vg[4 * tid + i]; dC.M[tid][i] = m[i]; }

        // GF(2) elimination for 4 distinct pivot bits
        int u[4], bp[4];
        #pragma unroll
        for (int i = 0; i < 4; ++i) {
            u[i] = m[i];
            for (int j = 0; j < i; ++j)
                if ((u[i] >> bp[j]) & 1) u[i] ^= u[j];
            bp[i] = 31 - __clz(u[i]);
            for (int j = 0; j < i; ++j)
                if ((u[j] >> bp[i]) & 1) u[j] ^= u[i];
        }
        #pragma unroll
        for (int a = 0; a < 3; ++a)
            #pragma unroll
            for (int bq = 0; bq < 3 - a; ++bq)
                if (bp[bq] > bp[bq + 1]) { int t = bp[bq]; bp[bq] = bp[bq + 1]; bp[bq + 1] = t; }
        #pragma unroll
        for (int i = 0; i < 4; ++i) dC.piv[tid][i] = bp[i];

        // parity LUTs over coset offsets V[t] = XOR of masks in t
        int V[16]; V[0] = 0;
        #pragma unroll
        for (int t = 1; t < 16; ++t) V[t] = V[t & (t - 1)] ^ m[__ffs(t) - 1];
        #pragma unroll
        for (int i = 0; i < 4; ++i) {
            int L = 0, f = fg[4 * tid + i];
            #pragma unroll
            for (int t = 0; t < 16; ++t) L |= (__popc(f & V[t]) & 1) << t;
            dC.lut[tid][i] = L;
        }
    }
}

// ---------------- packed f32x2 helpers ----------------
__device__ __forceinline__ u64 fma2(u64 a, u64 b, u64 c) {
    u64 d; asm("fma.rn.f32x2 %0, %1, %2, %3;" : "=l"(d) : "l"(a), "l"(b), "l"(c));
    return d;
}
__device__ __forceinline__ u64 mul2(u64 a, u64 b) {
    u64 d; asm("mul.rn.f32x2 %0, %1, %2;" : "=l"(d) : "l"(a), "l"(b));
    return d;
}
__device__ __forceinline__ u64 pk(float lo, float hi) {
    u64 d; asm("mov.b64 %0, {%1, %2};" : "=l"(d) : "f"(lo), "f"(hi));
    return d;
}
__device__ __forceinline__ void upk(u64 v, float& lo, float& hi) {
    asm("mov.b64 {%0, %1}, %2;" : "=f"(lo), "=f"(hi) : "l"(v));
}
__device__ __forceinline__ float sgnxor(float v, unsigned sb) {
    return __int_as_float(__float_as_int(v) ^ sb);
}

__device__ __forceinline__ int expand4(int p, const int* bp)
{
    #pragma unroll
    for (int i = 0; i < 4; ++i) {
        int m = (1 << bp[i]) - 1;
        p = ((p & ~m) << 1) | (p & m);
    }
    return p;
}

// ---------------- main kernel ----------------
__global__ __launch_bounds__(NTHREADS, 1)
void qnn_kernel(const float* __restrict__ x, float* __restrict__ out)
{
    extern __shared__ float smem[];
    float* sRe = smem;            // [QDIM]
    float* sIm = smem + QDIM;     // [QDIM]

    __shared__ Consts sC;
    __shared__ float cq[NQ], sq[NQ];
    __shared__ float tabLo[128], tabHi[128];
    __shared__ float redbuf[NTHREADS / 32];

    const int tid = threadIdx.x;
    const int b   = blockIdx.x;

    // copy constants to smem
    {
        const int n = (int)(sizeof(Consts) / 4);
        const int* src = (const int*)&dC;
        int* dst = (int*)&sC;
        for (int i = tid; i < n; i += NTHREADS) dst[i] = src[i];
    }

    if (tid < NQ) {
        float ang = x[b * NQ + tid] * 1.57079632679489662f;
        float s, c;
        sincosf(ang, &s, &c);
        cq[tid] = c;
        sq[tid] = s;
    }
    __syncthreads();

    // product-state tables (initial RY layer on |0...0>)
    if (tid < 128) {
        float p = 1.0f;
        #pragma unroll
        for (int k = 0; k < 7; ++k)
            p *= ((tid >> k) & 1) ? sq[NQ - 1 - k] : cq[NQ - 1 - k];
        tabLo[tid] = p;
    } else if (tid < 256) {
        int m = tid - 128;
        float p = 1.0f;
        #pragma unroll
        for (int k = 0; k < 7; ++k)
            p *= ((m >> k) & 1) ? sq[6 - k] : cq[6 - k];
        tabHi[m] = p;
    }
    __syncthreads();

    #pragma unroll
    for (int k = 0; k < QDIM / NTHREADS; ++k) {
        int j = tid + k * NTHREADS;
        sRe[j] = tabHi[j >> 7] * tabLo[j & 127];
        sIm[j] = 0.0f;
    }

    const u64 SGN = 0x8000000080000000ULL;

    // ---- 28 fused passes of 4 gates; two cosets per thread in f32x2 lanes ----
    for (int p = 0; p < NPASS; ++p) {
        __syncthreads();

        int mk[4];
        #pragma unroll
        for (int i = 0; i < 4; ++i) mk[i] = sC.M[p][i];

        const int jb0 = expand4(tid,            sC.piv[p]);
        const int jb1 = expand4(tid + NTHREADS, sC.piv[p]);

        // Gray-order load: position g = s ^ (s>>1)
        u64 Re[16], Im[16];
        {
            int j0 = jb0, j1 = jb1;
            #pragma unroll
            for (int s = 0; s < 16; ++s) {
                const int g = s ^ (s >> 1);
                Re[g] = pk(sRe[j0], sRe[j1]);
                Im[g] = pk(sIm[j0], sIm[j1]);
                if (s < 15) {
                    const int c = ((s + 1) & 1) ? 0 : (((s + 1) & 2) ? 1 : (((s + 1) & 4) ? 2 : 3));
                    j0 ^= mk[c];
                    j1 ^= mk[c];
                }
            }
        }

        #pragma unroll
        for (int i = 0; i < 4; ++i) {
            const float cz = sC.trig[p][i][0];
            const float sz = sC.trig[p][i][1];
            const float cy = sC.trig[p][i][2];
            const float sy = sC.trig[p][i][3];
            const int   f  = sC.F[p][i];
            const int   L  = sC.lut[p][i];

            const unsigned s0 = (unsigned)(__popc(f & jb0) & 1) << 31;
            const unsigned s1 = (unsigned)(__popc(f & jb1) & 1) << 31;

            // Pg/Qg used when L-bit == 1 (sigma = +1 for p==0 lanes)
            const u64 Pg  = pk(sgnxor(sz, s0), sgnxor(sz, s1));
            const u64 Qg  = pk(sgnxor(sy, s0), sgnxor(sy, s1));
            const u64 Pn  = Pg ^ SGN;
            const u64 Qn  = Qg ^ SGN;
            const u64 czv = pk(cz, cz);
            const u64 cyv = pk(cy, cy);

            #pragma unroll
            for (int t = 0; t < 16; ++t) {
                if (t & (1 << i)) continue;
                const int t1 = t | (1 << i);
                const bool lt = (L >> t) & 1;
                const u64 Pt  = lt ? Pg : Pn;
                const u64 Pnt = lt ? Pn : Pg;
                const u64 Qt  = lt ? Qg : Qn;
                const u64 Qnt = lt ? Qn : Qg;

                const u64 ar = Re[t],  ai = Im[t];
                const u64 br = Re[t1], bi = Im[t1];

                const u64 zr = fma2(ai, Pnt, mul2(ar, czv));   // ar*cz - ai*P
                const u64 zi = fma2(ar, Pt,  mul2(ai, czv));   // ar*P  + ai*cz
                const u64 wr = fma2(bi, Pt,  mul2(br, czv));   // br*cz + bi*P
                const u64 wi = fma2(br, Pnt, mul2(bi, czv));   // -br*P + bi*cz

                Re[t]  = fma2(wr, Qt,  mul2(zr, cyv));         // cy*z + Q*w
                Im[t]  = fma2(wi, Qt,  mul2(zi, cyv));
                Re[t1] = fma2(zr, Qnt, mul2(wr, cyv));         // cy*w - Q*z
                Im[t1] = fma2(zi, Qnt, mul2(wi, cyv));
            }
        }

        // Gray-order store
        {
            int j0 = jb0, j1 = jb1;
            #pragma unroll
            for (int s = 0; s < 16; ++s) {
                const int g = s ^ (s >> 1);
                float r0, r1, i0, i1;
                upk(Re[g], r0, r1);
                upk(Im[g], i0, i1);
                sRe[j0] = r0; sRe[j1] = r1;
                sIm[j0] = i0; sIm[j1] = i1;
                if (s < 15) {
                    const int c = ((s + 1) & 1) ? 0 : (((s + 1) & 2) ? 1 : (((s + 1) & 4) ? 2 : 3));
                    j0 ^= mk[c];
                    j1 ^= mk[c];
                }
            }
        }
    }
    __syncthreads();

    // ---- expectation value ----
    const int ff = sC.ffin;
    float acc = 0.0f;
    #pragma unroll
    for (int k = 0; k < QDIM / NTHREADS; ++k) {
        int j = tid + k * NTHREADS;
        float re = sRe[j], im = sIm[j];
        float pr = re * re + im * im;
        acc += (__popc(ff & j) & 1) ? -pr : pr;
    }
    #pragma unroll
    for (int off = 16; off > 0; off >>= 1)
        acc += __shfl_down_sync(0xffffffffu, acc, off);
    if ((tid & 31) == 0) redbuf[tid >> 5] = acc;
    __syncthreads();
    if (tid < 32) {
        float t = (tid < NTHREADS / 32) ? redbuf[tid] : 0.0f;
        #pragma unroll
        for (int off = 8; off > 0; off >>= 1)
            t += __shfl_down_sync(0xffffffffu, t, off);
        if (tid == 0) out[b] = (t + 1.0f) * 0.5f;
    }
}

extern "C" void kernel_launch(void* const* d_in, const int* in_sizes, int n_in,
                              void* d_out, int out_size)
{
    const float* x      = (const float*)d_in[0];   // (2048, 14)
    const float* params = (const float*)d_in[1];   // (224,)
    float* out          = (float*)d_out;           // (2048,)
    (void)in_sizes; (void)n_in;

    qnn_setup<<<1, 128>>>(params);

    const size_t shmem = (size_t)2 * QDIM * sizeof(float);   // 128 KB
    cudaFuncSetAttribute(qnn_kernel,
                         cudaFuncAttributeMaxDynamicSharedMemorySize,
                         (int)shmem);
    qnn_kernel<<<out_size, NTHREADS, shmem>>>(x, out);
}

// round 5
// speedup vs baseline: 1.1713x; 1.1713x over previous
#include <cuda_runtime.h>

// QNNClassifier: 14-qubit statevector, BATCH=2048, DEPTH=8.
// One CTA per batch element; state = QDIM float2 (interleaved re,im) in smem.
// CX gates deferred as GF(2) relabeling. Gates grouped 4+4+4+2 per layer so
// all gates in a pass share the same sigma frame => W = sigma^-1*sigma = I,
// letting a one-time per-thread coset-base correction (jb ^= V[parity bits])
// make slot-bit g == |0>/|1> role of gate g. Inner butterfly is sign-free.
// Arithmetic is packed f32x2 over (re,im) lanes: 8 fma-pipe ops per pair.

#define NQ       14
#define QDIM     16384
#define DEPTH    8
#define NGATES   (DEPTH * NQ)   // 112
#define NPASSES  (DEPTH * 4)    // 32 (4+4+4+2 per layer)
#define NTHREADS 1024

typedef unsigned long long u64;

struct Consts {
    int   piv[NPASSES][4];      // sorted pivot bits for coset enumeration
    int   V[NPASSES][16];       // XOR offsets over slot index
    int   F[NPASSES][4];        // parity masks per gate
    float trig[NPASSES][4][4];  // cz, sz, cy, sy
    int   ffin;
};
__device__ Consts dC;

// ---------------- setup kernel ----------------
__global__ void qnn_setup(const float* __restrict__ params)
{
    __shared__ int vg[NGATES], fg[NGATES];
    const int tid = threadIdx.x;

    if (tid == 0) {
        int v[NQ], f[NQ];
        #pragma unroll
        for (int q = 0; q < NQ; ++q) { v[q] = 1 << (NQ - 1 - q); f[q] = v[q]; }
        for (int l = 0; l < DEPTH; ++l) {
            for (int q = 0; q < NQ; ++q) { fg[l * NQ + q] = f[q]; vg[l * NQ + q] = v[q]; }
            for (int c = 0; c < NQ; ++c) {        // CX ring after the layer
                int t = (c + 1) % NQ;
                v[c] ^= v[t];
                f[t] ^= f[c];
            }
        }
        dC.ffin = f[0];
    }
    __syncthreads();

    if (tid < NGATES) {                            // trig per gate
        int l = tid / NQ, q = tid % NQ;
        int grp = q >> 2; if (grp > 3) grp = 3;
        int p = l * 4 + grp, i = q - grp * 4;
        float tz = params[2 * tid];
        float ty = params[2 * tid + 1];
        float sz, cz, sy, cy;
        sincosf(0.5f * tz, &sz, &cz);
        sincosf(0.5f * ty, &sy, &cy);
        dC.trig[p][i][0] = cz; dC.trig[p][i][1] = sz;
        dC.trig[p][i][2] = cy; dC.trig[p][i][3] = sy;
        dC.F[p][i] = fg[l * NQ + q];
    }

    if (tid < NPASSES) {
        int l = tid >> 2, grp = tid & 3;
        int cnt = (grp == 3) ? 2 : 4;
        int m[4] = {0, 0, 0, 0};
        for (int i = 0; i < cnt; ++i) m[i] = vg[l * NQ + grp * 4 + i];

        // GF(2) elimination: cnt distinct pivot bits (prefer high bits)
        int u[4], bp[4];
        for (int i = 0; i < cnt; ++i) {
            u[i] = m[i];
            for (int j = 0; j < i; ++j)
                if ((u[i] >> bp[j]) & 1) u[i] ^= u[j];
            bp[i] = 31 - __clz(u[i]);
            for (int j = 0; j < i; ++j)
                if ((u[j] >> bp[i]) & 1) u[j] ^= u[i];
        }
        for (int a = 0; a < cnt - 1; ++a)
            for (int bq = 0; bq < cnt - 1 - a; ++bq)
                if (bp[bq] > bp[bq + 1]) { int t = bp[bq]; bp[bq] = bp[bq + 1]; bp[bq + 1] = t; }
        for (int i = 0; i < 4; ++i) dC.piv[tid][i] = (i < cnt) ? bp[i] : 0;

        int V[16]; V[0] = 0;
        for (int t = 1; t < (1 << cnt); ++t) V[t] = V[t & (t - 1)] ^ m[__ffs(t) - 1];
        for (int t = 0; t < 16; ++t) dC.V[tid][t] = (t < (1 << cnt)) ? V[t] : 0;
    }
}

// ---------------- packed f32x2 helpers ----------------
__device__ __forceinline__ u64 fma2(u64 a, u64 b, u64 c) {
    u64 d; asm("fma.rn.f32x2 %0, %1, %2, %3;" : "=l"(d) : "l"(a), "l"(b), "l"(c));
    return d;
}
__device__ __forceinline__ u64 mul2(u64 a, u64 b) {
    u64 d; asm("mul.rn.f32x2 %0, %1, %2;" : "=l"(d) : "l"(a), "l"(b));
    return d;
}
__device__ __forceinline__ u64 pk(float lo, float hi) {
    u64 d; asm("mov.b64 %0, {%1, %2};" : "=l"(d) : "f"(lo), "f"(hi));
    return d;
}
// K-(X) = ( im, -re):  lo = X.hi,        hi = X.lo ^ sign
__device__ __forceinline__ u64 kminus(u64 x) {
    u64 r;
    asm("{\n\t.reg .b32 l,h;\n\t"
        "mov.b64 {l,h}, %1;\n\t"
        "xor.b32 l, l, 0x80000000;\n\t"
        "mov.b64 %0, {h, l};\n\t}" : "=l"(r) : "l"(x));
    return r;
}
// K+(X) = (-im,  re):  lo = X.hi ^ sign, hi = X.lo
__device__ __forceinline__ u64 kplus(u64 x) {
    u64 r;
    asm("{\n\t.reg .b32 l,h;\n\t"
        "mov.b64 {l,h}, %1;\n\t"
        "xor.b32 h, h, 0x80000000;\n\t"
        "mov.b64 %0, {h, l};\n\t}" : "=l"(r) : "l"(x));
    return r;
}

__device__ __forceinline__ int expand4(int p, const int* bp)
{
    #pragma unroll
    for (int i = 0; i < 4; ++i) {
        int m = (1 << bp[i]) - 1;
        p = ((p & ~m) << 1) | (p & m);
    }
    return p;
}
__device__ __forceinline__ int expand2(int p, const int* bp)
{
    #pragma unroll
    for (int i = 0; i < 2; ++i) {
        int m = (1 << bp[i]) - 1;
        p = ((p & ~m) << 1) | (p & m);
    }
    return p;
}

// one canonical butterfly: A = |0> slot, B = |1> slot
// z = A*(cz - i sz), w = B*(cz + i sz); A' = cy z - sy w; B' = sy z + cy w
__device__ __forceinline__ void bfly(u64& A, u64& B,
                                     u64 czv, u64 szv, u64 cyv, u64 syv, u64 synv)
{
    u64 z = fma2(kminus(A), szv, mul2(A, czv));
    u64 w = fma2(kplus(B),  szv, mul2(B, czv));
    A = fma2(w, synv, mul2(z, cyv));
    B = fma2(z, syv,  mul2(w, cyv));
}

// ---------------- main kernel ----------------
__global__ __launch_bounds__(NTHREADS, 1)
void qnn_kernel(const float* __restrict__ x, float* __restrict__ out)
{
    extern __shared__ u64 sAmp[];                // [QDIM] packed (re,im)

    __shared__ Consts sC;
    __shared__ float cq[NQ], sq[NQ];
    __shared__ float tabLo[128], tabHi[128];
    __shared__ float redbuf[NTHREADS / 32];

    const int tid = threadIdx.x;
    const int b   = blockIdx.x;

    {   // copy constants to smem
        const int n = (int)(sizeof(Consts) / 4);
        const int* src = (const int*)&dC;
        int* dst = (int*)&sC;
        for (int i = tid; i < n; i += NTHREADS) dst[i] = src[i];
    }

    if (tid < NQ) {
        float ang = x[b * NQ + tid] * 1.57079632679489662f;
        float s, c;
        sincosf(ang, &s, &c);
        cq[tid] = c;
        sq[tid] = s;
    }
    __syncthreads();

    // product-state tables (initial RY layer on |0...0>)
    if (tid < 128) {
        float p = 1.0f;
        #pragma unroll
        for (int k = 0; k < 7; ++k)
            p *= ((tid >> k) & 1) ? sq[NQ - 1 - k] : cq[NQ - 1 - k];
        tabLo[tid] = p;
    } else if (tid < 256) {
        int m = tid - 128;
        float p = 1.0f;
        #pragma unroll
        for (int k = 0; k < 7; ++k)
            p *= ((m >> k) & 1) ? sq[6 - k] : cq[6 - k];
        tabHi[m] = p;
    }
    __syncthreads();

    #pragma unroll
    for (int k = 0; k < QDIM / NTHREADS; ++k) {
        int j = tid + k * NTHREADS;
        sAmp[j] = pk(tabHi[j >> 7] * tabLo[j & 127], 0.0f);
    }

    // ---- 32 passes (per layer: 4,4,4 then 2 gates) ----
    for (int p = 0; p < NPASSES; ++p) {
        __syncthreads();

        if ((p & 3) != 3) {
            // ======== 4-gate pass: one 16-amp coset per thread ========
            int mk[4];
            #pragma unroll
            for (int i = 0; i < 4; ++i) mk[i] = sC.V[p][1 << i];

            int jb = expand4(tid, sC.piv[p]);
            // canonical-base correction: slot-bit g == |0>/|1> role of gate g
            {
                int bb = 0;
                #pragma unroll
                for (int g = 0; g < 4; ++g)
                    bb |= (__popc(sC.F[p][g] & jb) & 1) << g;
                jb ^= sC.V[p][bb];
            }

            u64 A[16];
            {   // Gray-order load
                int j = jb;
                #pragma unroll
                for (int s = 0; s < 16; ++s) {
                    const int g = s ^ (s >> 1);
                    A[g] = sAmp[j];
                    if (s < 15) {
                        const int c = ((s + 1) & 1) ? 0 : (((s + 1) & 2) ? 1 : (((s + 1) & 4) ? 2 : 3));
                        j ^= mk[c];
                    }
                }
            }

            #pragma unroll
            for (int i = 0; i < 4; ++i) {
                const float cz = sC.trig[p][i][0];
                const float sz = sC.trig[p][i][1];
                const float cy = sC.trig[p][i][2];
                const float sy = sC.trig[p][i][3];
                const u64 czv = pk(cz, cz), szv = pk(sz, sz);
                const u64 cyv = pk(cy, cy), syv = pk(sy, sy);
                const u64 synv = syv ^ 0x8000000080000000ULL;

                #pragma unroll
                for (int t = 0; t < 16; ++t) {
                    if (t & (1 << i)) continue;
                    bfly(A[t], A[t | (1 << i)], czv, szv, cyv, syv, synv);
                }
            }

            {   // Gray-order store
                int j = jb;
                #pragma unroll
                for (int s = 0; s < 16; ++s) {
                    const int g = s ^ (s >> 1);
                    sAmp[j] = A[g];
                    if (s < 15) {
                        const int c = ((s + 1) & 1) ? 0 : (((s + 1) & 2) ? 1 : (((s + 1) & 4) ? 2 : 3));
                        j ^= mk[c];
                    }
                }
            }
        } else {
            // ======== 2-gate pass: four 4-amp cosets per thread ========
            const int m0 = sC.V[p][1], m1 = sC.V[p][2];
            const int f0 = sC.F[p][0], f1 = sC.F[p][1];

            const float cz0 = sC.trig[p][0][0], sz0 = sC.trig[p][0][1];
            const float cy0 = sC.trig[p][0][2], sy0 = sC.trig[p][0][3];
            const float cz1 = sC.trig[p][1][0], sz1 = sC.trig[p][1][1];
            const float cy1 = sC.trig[p][1][2], sy1 = sC.trig[p][1][3];
            const u64 czv0 = pk(cz0, cz0), szv0 = pk(sz0, sz0);
            const u64 cyv0 = pk(cy0, cy0), syv0 = pk(sy0, sy0);
            const u64 synv0 = syv0 ^ 0x8000000080000000ULL;
            const u64 czv1 = pk(cz1, cz1), szv1 = pk(sz1, sz1);
            const u64 cyv1 = pk(cy1, cy1), syv1 = pk(sy1, sy1);
            const u64 synv1 = syv1 ^ 0x8000000080000000ULL;

            #pragma unroll
            for (int kk = 0; kk < 4; ++kk) {
                int jb = expand2(tid + kk * NTHREADS, sC.piv[p]);
                int bb = (__popc(f0 & jb) & 1) | ((__popc(f1 & jb) & 1) << 1);
                jb ^= sC.V[p][bb];

                const int j0 = jb, j1 = jb ^ m0, j2 = jb ^ m1, j3 = jb ^ m0 ^ m1;
                u64 a0 = sAmp[j0], a1 = sAmp[j1], a2 = sAmp[j2], a3 = sAmp[j3];

                bfly(a0, a1, czv0, szv0, cyv0, syv0, synv0);   // gate 0: pairs (0,1),(2,3)
                bfly(a2, a3, czv0, szv0, cyv0, syv0, synv0);
                bfly(a0, a2, czv1, szv1, cyv1, syv1, synv1);   // gate 1: pairs (0,2),(1,3)
                bfly(a1, a3, czv1, szv1, cyv1, syv1, synv1);

                sAmp[j0] = a0; sAmp[j1] = a1; sAmp[j2] = a2; sAmp[j3] = a3;
            }
        }
    }
    __syncthreads();

    // ---- expectation value ----
    const int ff = sC.ffin;
    const float2* sF2 = (const float2*)sAmp;
    float acc = 0.0f;
    #pragma unroll
    for (int k = 0; k < QDIM / NTHREADS; ++k) {
        int j = tid + k * NTHREADS;
        float2 a = sF2[j];
        float pr = a.x * a.x + a.y * a.y;
        acc += (__popc(ff & j) & 1) ? -pr : pr;
    }
    #pragma unroll
    for (int off = 16; off > 0; off >>= 1)
        acc += __shfl_down_sync(0xffffffffu, acc, off);
    if ((tid & 31) == 0) redbuf[tid >> 5] = acc;
    __syncthreads();
    if (tid < 32) {
        float t = redbuf[tid];
        #pragma unroll
        for (int off = 16; off > 0; off >>= 1)
            t += __shfl_down_sync(0xffffffffu, t, off);
        if (tid == 0) out[b] = (t + 1.0f) * 0.5f;
    }
}

extern "C" void kernel_launch(void* const* d_in, const int* in_sizes, int n_in,
                              void* d_out, int out_size)
{
    const float* x      = (const float*)d_in[0];   // (2048, 14)
    const float* params = (const float*)d_in[1];   // (224,)
    float* out          = (float*)d_out;           // (2048,)
    (void)in_sizes; (void)n_in;

    qnn_setup<<<1, 128>>>(params);

    const size_t shmem = (size_t)QDIM * sizeof(u64);   // 128 KB
    cudaFuncSetAttribute(qnn_kernel,
                         cudaFuncAttributeMaxDynamicSharedMemorySize,
                         (int)shmem);
    qnn_kernel<<<out_size, NTHREADS, shmem>>>(x, out);
}

// round 6
// speedup vs baseline: 1.3338x; 1.1388x over previous
#include <cuda_runtime.h>

// QNNClassifier: 14-qubit statevector, BATCH=2048, DEPTH=8.
// One CTA/batch element; state = QDIM packed (re,im) u64 in smem (128 KB).
// CX deferred as GF(2) relabeling. Per layer gates grouped 4+4+4+2 (same
// sigma frame => W=I). Each pass = diagonal phase stage (all RZs collapsed
// into 16 precomputed complex constants, base parity folded via index t^bb)
// followed by REAL RY butterflies on packed f32x2 (no lane swaps).
// Coset enumeration keeps warp-lane low nibbles distinct (fixTab) so all
// LDS.64/STS.64 are bank-conflict-free.

#define NQ       14
#define QDIM     16384
#define DEPTH    8
#define NGATES   (DEPTH * NQ)   // 112
#define NPASSES  (DEPTH * 4)    // 32
#define NTHREADS 1024

typedef unsigned long long u64;
typedef unsigned int u32;

struct __align__(128) Consts {
    u64   Pc[NPASSES][16];      // phase cos, packed (c,c)
    u64   Ps[NPASSES][16];      // phase sin, packed (s,s)
    int   piv[NPASSES][4];      // sorted pivot bits
    int   V[NPASSES][16];       // coset XOR offsets over slot index
    int   F[NPASSES][4];        // parity masks per gate
    float cy[NPASSES][4];
    float sy[NPASSES][4];
    int   fixTab[NPASSES][16];  // low-nibble bank fixup
    int   fixShift[NPASSES];
    int   ffin;
};
__device__ Consts dC;

__device__ __forceinline__ u64 splat_bits(float v) {
    u32 b = __float_as_uint(v);
    return ((u64)b << 32) | (u64)b;
}

// ---------------- setup kernel (512 threads, 1 block) ----------------
__global__ void qnn_setup(const float* __restrict__ params)
{
    __shared__ int vg[NGATES], fg[NGATES];
    const int tid = threadIdx.x;

    if (tid == 0) {
        int v[NQ], f[NQ];
        #pragma unroll
        for (int q = 0; q < NQ; ++q) { v[q] = 1 << (NQ - 1 - q); f[q] = v[q]; }
        for (int l = 0; l < DEPTH; ++l) {
            for (int q = 0; q < NQ; ++q) { fg[l * NQ + q] = f[q]; vg[l * NQ + q] = v[q]; }
            for (int c = 0; c < NQ; ++c) {          // CX ring after the layer
                int t = (c + 1) % NQ;
                v[c] ^= v[t];
                f[t] ^= f[c];
            }
        }
        dC.ffin = f[0];
    }
    __syncthreads();

    if (tid < NGATES) {                              // RY trig + parity mask
        int l = tid / NQ, q = tid % NQ;
        int grp = q >> 2; if (grp > 3) grp = 3;
        int p = l * 4 + grp, i = q - grp * 4;
        float ty = params[2 * tid + 1];
        float sy, cy;
        sincosf(0.5f * ty, &sy, &cy);
        dC.cy[p][i] = cy;
        dC.sy[p][i] = sy;
        dC.F[p][i]  = fg[tid];
    }

    if (tid < NPASSES) {                             // pass geometry
        int l = tid >> 2, grp = tid & 3;
        int cnt = (grp == 3) ? 2 : 4;
        int m[4] = {0, 0, 0, 0};
        for (int i = 0; i < cnt; ++i) m[i] = vg[l * NQ + grp * 4 + i];

        // GF(2) elimination; prefer pivot bits >= 4 (bank-friendly)
        int u[4], bp[4];
        for (int i = 0; i < cnt; ++i) {
            u[i] = m[i];
            for (int j = 0; j < i; ++j)
                if ((u[i] >> bp[j]) & 1) u[i] ^= u[j];
            int hi = u[i] & ~0xF;
            bp[i] = hi ? (31 - __clz(hi)) : (31 - __clz(u[i]));
            for (int j = 0; j < i; ++j)
                if ((u[j] >> bp[i]) & 1) u[j] ^= u[i];
        }
        for (int a = 0; a < cnt - 1; ++a)            // sort ascending
            for (int bq = 0; bq < cnt - 1 - a; ++bq)
                if (bp[bq] > bp[bq + 1]) { int t = bp[bq]; bp[bq] = bp[bq + 1]; bp[bq + 1] = t; }
        for (int i = 0; i < 4; ++i) dC.piv[tid][i] = (i < cnt) ? bp[i] : 30;

        int V[16]; V[0] = 0;
        for (int t = 1; t < (1 << cnt); ++t) V[t] = V[t & (t - 1)] ^ m[__ffs(t) - 1];
        for (int t = 0; t < 16; ++t) dC.V[tid][t] = (t < (1 << cnt)) ? V[t] : 0;

        // low-nibble fixup: copy spare p-bits into pivot positions < 4
        int lowPiv[4], k = 0;
        for (int i = 0; i < cnt; ++i)
            if (bp[i] < 4) lowPiv[k++] = bp[i];
        dC.fixShift[tid] = 4 - k;
        for (int v = 0; v < 16; ++v) {
            int fv = 0;
            for (int i = 0; i < k; ++i)
                if ((v >> i) & 1) fv |= 1 << lowPiv[i];
            dC.fixTab[tid][v] = fv;
        }
    }

    // phase tables: P0[t] = exp(i * sum_i (t_i ? +1 : -1) * tz_i / 2)
    if (tid < NPASSES * 16) {
        int p = tid >> 4, t = tid & 15;
        int l = p >> 2, grp = p & 3;
        int cnt = (grp == 3) ? 2 : 4;
        float phi = 0.0f;
        if (t < (1 << cnt)) {
            for (int i = 0; i < cnt; ++i) {
                float tz = params[2 * (l * NQ + grp * 4 + i)];
                phi += ((t >> i) & 1) ? 0.5f * tz : -0.5f * tz;
            }
        }
        float s, c;
        sincosf(phi, &s, &c);
        dC.Pc[p][t] = splat_bits(c);
        dC.Ps[p][t] = splat_bits(s);
    }
}

// ---------------- packed f32x2 helpers ----------------
__device__ __forceinline__ u64 fma2(u64 a, u64 b, u64 c) {
    u64 d; asm("fma.rn.f32x2 %0, %1, %2, %3;" : "=l"(d) : "l"(a), "l"(b), "l"(c));
    return d;
}
__device__ __forceinline__ u64 mul2(u64 a, u64 b) {
    u64 d; asm("mul.rn.f32x2 %0, %1, %2;" : "=l"(d) : "l"(a), "l"(b));
    return d;
}
// kplus(x) = (-im, re)
__device__ __forceinline__ u64 kplus(u64 x) {
    u64 r;
    asm("{\n\t.reg .b32 l,h;\n\t"
        "mov.b64 {l,h}, %1;\n\t"
        "xor.b32 h, h, 0x80000000;\n\t"
        "mov.b64 %0, {h, l};\n\t}" : "=l"(r) : "l"(x));
    return r;
}

__device__ __forceinline__ int expand4(int p, const int* bp)
{
    #pragma unroll
    for (int i = 0; i < 4; ++i) {
        int m = (1 << bp[i]) - 1;
        p = ((p & ~m) << 1) | (p & m);
    }
    return p;
}
__device__ __forceinline__ int expand2(int p, const int* bp)
{
    #pragma unroll
    for (int i = 0; i < 2; ++i) {
        int m = (1 << bp[i]) - 1;
        p = ((p & ~m) << 1) | (p & m);
    }
    return p;
}

#define SGNALL 0x8000000080000000ULL

// ---------------- main kernel ----------------
__global__ __launch_bounds__(NTHREADS, 1)
void qnn_kernel(const float* __restrict__ x, float* __restrict__ out)
{
    extern __shared__ u64 sAmp[];                  // [QDIM] packed (re,im)

    __shared__ Consts sC;
    __shared__ float cq[NQ], sq[NQ];
    __shared__ float tabLo[128], tabHi[128];
    __shared__ float redbuf[NTHREADS / 32];

    const int tid = threadIdx.x;
    const int b   = blockIdx.x;

    {   // copy constants to smem
        const int n = (int)(sizeof(Consts) / 4);
        const int* src = (const int*)&dC;
        int* dst = (int*)&sC;
        for (int i = tid; i < n; i += NTHREADS) dst[i] = src[i];
    }

    if (tid < NQ) {
        float ang = x[b * NQ + tid] * 1.57079632679489662f;
        float s, c;
        sincosf(ang, &s, &c);
        cq[tid] = c;
        sq[tid] = s;
    }
    __syncthreads();

    // product-state tables (initial RY layer on |0...0>)
    if (tid < 128) {
        float p = 1.0f;
        #pragma unroll
        for (int k = 0; k < 7; ++k)
            p *= ((tid >> k) & 1) ? sq[NQ - 1 - k] : cq[NQ - 1 - k];
        tabLo[tid] = p;
    } else if (tid < 256) {
        int m = tid - 128;
        float p = 1.0f;
        #pragma unroll
        for (int k = 0; k < 7; ++k)
            p *= ((m >> k) & 1) ? sq[6 - k] : cq[6 - k];
        tabHi[m] = p;
    }
    __syncthreads();

    #pragma unroll
    for (int k = 0; k < QDIM / NTHREADS; ++k) {
        int j = tid + k * NTHREADS;
        u32 re = __float_as_uint(tabHi[j >> 7] * tabLo[j & 127]);
        sAmp[j] = (u64)re;                          // im = 0 in high word
    }

    // ---- 32 passes (per layer: 4,4,4 then 2 gates) ----
    for (int p = 0; p < NPASSES; ++p) {
        __syncthreads();

        const u64* pc = sC.Pc[p];
        const u64* ps = sC.Ps[p];

        if ((p & 3) != 3) {
            // ======== 4-gate pass: one 16-amp coset per thread ========
            int mk[4];
            #pragma unroll
            for (int i = 0; i < 4; ++i) mk[i] = sC.V[p][1 << i];

            int jb = expand4(tid, sC.piv[p]);
            jb ^= sC.fixTab[p][(tid >> sC.fixShift[p]) & 15];

            int bb = 0;
            #pragma unroll
            for (int g = 0; g < 4; ++g)
                bb |= (__popc(sC.F[p][g] & jb) & 1) << g;

            // Gray-order load + phase multiply  a *= (c + i s)
            u64 A[16];
            {
                int j = jb;
                #pragma unroll
                for (int s = 0; s < 16; ++s) {
                    const int g = s ^ (s >> 1);
                    u64 a  = sAmp[j];
                    u64 cv = pc[g ^ bb];
                    u64 sv = ps[g ^ bb];
                    A[g] = fma2(kplus(a), sv, mul2(a, cv));
                    if (s < 15) {
                        const int c = ((s + 1) & 1) ? 0 : (((s + 1) & 2) ? 1 : (((s + 1) & 4) ? 2 : 3));
                        j ^= mk[c];
                    }
                }
            }

            // 4 real RY butterflies
            #pragma unroll
            for (int i = 0; i < 4; ++i) {
                u32 sb = ((u32)((bb >> i) & 1)) << 31;
                u64 sg = ((u64)sb << 32) | (u64)sb;
                const u64 cyv  = splat_bits(sC.cy[p][i]);
                const u64 syv  = splat_bits(sC.sy[p][i]) ^ sg;
                const u64 synv = syv ^ SGNALL;

                #pragma unroll
                for (int t = 0; t < 16; ++t) {
                    if (t & (1 << i)) continue;
                    const int t1 = t | (1 << i);
                    u64 Av = A[t], Bv = A[t1];
                    A[t]  = fma2(Bv, synv, mul2(Av, cyv));   // cy*A - sy*B
                    A[t1] = fma2(Av, syv,  mul2(Bv, cyv));   // sy*A + cy*B
                }
            }

            // Gray-order store
            {
                int j = jb;
                #pragma unroll
                for (int s = 0; s < 16; ++s) {
                    const int g = s ^ (s >> 1);
                    sAmp[j] = A[g];
                    if (s < 15) {
                        const int c = ((s + 1) & 1) ? 0 : (((s + 1) & 2) ? 1 : (((s + 1) & 4) ? 2 : 3));
                        j ^= mk[c];
                    }
                }
            }
        } else {
            // ======== 2-gate pass: four 4-amp cosets per thread ========
            const int m0 = sC.V[p][1], m1 = sC.V[p][2], m01 = sC.V[p][3];
            const int f0 = sC.F[p][0], f1 = sC.F[p][1];
            const int fsh = sC.fixShift[p];

            const u64 cy0 = splat_bits(sC.cy[p][0]);
            const u64 sy0b = splat_bits(sC.sy[p][0]);
            const u64 cy1 = splat_bits(sC.cy[p][1]);
            const u64 sy1b = splat_bits(sC.sy[p][1]);

            #pragma unroll
            for (int kk = 0; kk < 4; ++kk) {
                const int pp = tid + kk * NTHREADS;
                int jb = expand2(pp, sC.piv[p]);
                jb ^= sC.fixTab[p][(pp >> fsh) & 15];

                const int b0 = __popc(f0 & jb) & 1;
                const int b1 = __popc(f1 & jb) & 1;
                const int bb = b0 | (b1 << 1);

                const int j0 = jb, j1 = jb ^ m0, j2 = jb ^ m1, j3 = jb ^ m01;

                u64 a0 = sAmp[j0], a1 = sAmp[j1], a2 = sAmp[j2], a3 = sAmp[j3];
                a0 = fma2(kplus(a0), ps[0 ^ bb], mul2(a0, pc[0 ^ bb]));
                a1 = fma2(kplus(a1), ps[1 ^ bb], mul2(a1, pc[1 ^ bb]));
                a2 = fma2(kplus(a2), ps[2 ^ bb], mul2(a2, pc[2 ^ bb]));
                a3 = fma2(kplus(a3), ps[3 ^ bb], mul2(a3, pc[3 ^ bb]));

                {   // gate 0: pairs (0,1),(2,3)
                    u32 sb = ((u32)b0) << 31;
                    u64 sg = ((u64)sb << 32) | (u64)sb;
                    u64 syv = sy0b ^ sg, synv = syv ^ SGNALL;
                    u64 t;
                    t  = fma2(a1, synv, mul2(a0, cy0));
                    a1 = fma2(a0, syv,  mul2(a1, cy0));
                    a0 = t;
                    t  = fma2(a3, synv, mul2(a2, cy0));
                    a3 = fma2(a2, syv,  mul2(a3, cy0));
                    a2 = t;
                }
                {   // gate 1: pairs (0,2),(1,3)
                    u32 sb = ((u32)b1) << 31;
                    u64 sg = ((u64)sb << 32) | (u64)sb;
                    u64 syv = sy1b ^ sg, synv = syv ^ SGNALL;
                    u64 t;
                    t  = fma2(a2, synv, mul2(a0, cy1));
                    a2 = fma2(a0, syv,  mul2(a2, cy1));
                    a0 = t;
                    t  = fma2(a3, synv, mul2(a1, cy1));
                    a3 = fma2(a1, syv,  mul2(a3, cy1));
                    a1 = t;
                }

                sAmp[j0] = a0; sAmp[j1] = a1; sAmp[j2] = a2; sAmp[j3] = a3;
            }
        }
    }
    __syncthreads();

    // ---- expectation value ----
    const int ff = sC.ffin;
    const float2* sF2 = (const float2*)sAmp;
    float acc = 0.0f;
    #pragma unroll
    for (int k = 0; k < QDIM / NTHREADS; ++k) {
        int j = tid + k * NTHREADS;
        float2 a = sF2[j];
        float pr = a.x * a.x + a.y * a.y;
        acc += (__popc(ff & j) & 1) ? -pr : pr;
    }
    #pragma unroll
    for (int off = 16; off > 0; off >>= 1)
        acc += __shfl_down_sync(0xffffffffu, acc, off);
    if ((tid & 31) == 0) redbuf[tid >> 5] = acc;
    __syncthreads();
    if (tid < 32) {
        float t = redbuf[tid];
        #pragma unroll
        for (int off = 16; off > 0; off >>= 1)
            t += __shfl_down_sync(0xffffffffu, t, off);
        if (tid == 0) out[b] = (t + 1.0f) * 0.5f;
    }
}

extern "C" void kernel_launch(void* const* d_in, const int* in_sizes, int n_in,
                              void* d_out, int out_size)
{
    const float* x      = (const float*)d_in[0];   // (2048, 14)
    const float* params = (const float*)d_in[1];   // (224,)
    float* out          = (float*)d_out;           // (2048,)
    (void)in_sizes; (void)n_in;

    qnn_setup<<<1, 512>>>(params);

    const size_t shmem = (size_t)QDIM * sizeof(u64);   // 128 KB
    cudaFuncSetAttribute(qnn_kernel,
                         cudaFuncAttributeMaxDynamicSharedMemorySize,
                         (int)shmem);
    qnn_kernel<<<out_size, NTHREADS, shmem>>>(x, out);
}

// round 7
// speedup vs baseline: 1.5919x; 1.1934x over previous
#include <cuda_runtime.h>

// QNNClassifier: 14-qubit statevector, BATCH=2048, DEPTH=8.
// One CTA/batch element; state = QDIM packed (re,im) u64 in smem (128 KB).
// CX deferred as GF(2) relabeling; per layer gates grouped 4+4+4+2 (same
// sigma frame => W=I, slot bit g == gate-g parity up to per-thread bb).
// Pass = diagonal RZ-phase stage (scalar 4-FFMA complex multiply; constants
// from a conj-compressed 8-entry table replicated across 16 lane columns ->
// bank-conflict-free) + RY stage as 3-shear butterflies (3 fma2/pair, exact).

#define NQ       14
#define QDIM     16384
#define DEPTH    8
#define NGATES   (DEPTH * NQ)   // 112
#define NPASSES  (DEPTH * 4)    // 32
#define NTHREADS 1024

typedef unsigned long long u64;
typedef unsigned int u32;

struct __align__(16) Consts {
    float2 Pcs[NPASSES][8];     // phase (cos, sin) for slots h=0..7 (conj half derived)
    int    piv[NPASSES][4];     // sorted pivot bits
    int    V[NPASSES][16];      // coset XOR offsets over slot index
    int    F[NPASSES][4];       // parity masks per gate
    float  tq[NPASSES][4];      // tan(ty/4)  (shear constant)
    float  sy[NPASSES][4];      // sin(ty/2)
    int    fixTab[NPASSES][16]; // low-nibble bank fixup
    int    fixShift[NPASSES];
    int    ffin;
};
__device__ Consts dC;

// ---------------- setup kernel (512 threads, 1 block) ----------------
__global__ void qnn_setup(const float* __restrict__ params)
{
    __shared__ int vg[NGATES], fg[NGATES];
    const int tid = threadIdx.x;

    if (tid == 0) {
        int v[NQ], f[NQ];
        #pragma unroll
        for (int q = 0; q < NQ; ++q) { v[q] = 1 << (NQ - 1 - q); f[q] = v[q]; }
        for (int l = 0; l < DEPTH; ++l) {
            for (int q = 0; q < NQ; ++q) { fg[l * NQ + q] = f[q]; vg[l * NQ + q] = v[q]; }
            for (int c = 0; c < NQ; ++c) {          // CX ring after the layer
                int t = (c + 1) % NQ;
                v[c] ^= v[t];
                f[t] ^= f[c];
            }
        }
        dC.ffin = f[0];
    }
    __syncthreads();

    if (tid < NGATES) {                              // RY shear constants
        int l = tid / NQ, q = tid % NQ;
        int grp = q >> 2; if (grp > 3) grp = 3;
        int p = l * 4 + grp, i = q - grp * 4;
        float ty = params[2 * tid + 1];
        dC.tq[p][i] = tanf(0.25f * ty);
        dC.sy[p][i] = sinf(0.5f * ty);
        dC.F[p][i]  = fg[tid];
    }

    if (tid < NPASSES) {                             // pass geometry
        int l = tid >> 2, grp = tid & 3;
        int cnt = (grp == 3) ? 2 : 4;
        int m[4] = {0, 0, 0, 0};
        for (int i = 0; i < cnt; ++i) m[i] = vg[l * NQ + grp * 4 + i];

        // GF(2) elimination; prefer pivot bits >= 4 (bank-friendly)
        int u[4], bp[4];
        for (int i = 0; i < cnt; ++i) {
            u[i] = m[i];
            for (int j = 0; j < i; ++j)
                if ((u[i] >> bp[j]) & 1) u[i] ^= u[j];
            int hi = u[i] & ~0xF;
            bp[i] = hi ? (31 - __clz(hi)) : (31 - __clz(u[i]));
            for (int j = 0; j < i; ++j)
                if ((u[j] >> bp[i]) & 1) u[j] ^= u[i];
        }
        for (int a = 0; a < cnt - 1; ++a)            // sort ascending
            for (int bq = 0; bq < cnt - 1 - a; ++bq)
                if (bp[bq] > bp[bq + 1]) { int t = bp[bq]; bp[bq] = bp[bq + 1]; bp[bq + 1] = t; }
        for (int i = 0; i < 4; ++i) dC.piv[tid][i] = (i < cnt) ? bp[i] : 30;

        int V[16]; V[0] = 0;
        for (int t = 1; t < (1 << cnt); ++t) V[t] = V[t & (t - 1)] ^ m[__ffs(t) - 1];
        for (int t = 0; t < 16; ++t) dC.V[tid][t] = (t < (1 << cnt)) ? V[t] : 0;

        // low-nibble fixup: copy spare p-bits into pivot positions < 4
        int lowPiv[4], k = 0;
        for (int i = 0; i < cnt; ++i)
            if (bp[i] < 4) lowPiv[k++] = bp[i];
        dC.fixShift[tid] = 4 - k;
        for (int v = 0; v < 16; ++v) {
            int fv = 0;
            for (int i = 0; i < k; ++i)
                if ((v >> i) & 1) fv |= 1 << lowPiv[i];
            dC.fixTab[tid][v] = fv;
        }
    }

    // phase table: Pcs[p][h] = (cos, sin) of phi(h) = sum_i (h_i? +:-) tz_i/2
    if (tid < NPASSES * 8) {
        int p = tid >> 3, h = tid & 7;
        int l = p >> 2, grp = p & 3;
        int cnt = (grp == 3) ? 2 : 4;
        float phi = 0.0f;
        for (int i = 0; i < cnt; ++i) {
            float tz = params[2 * (l * NQ + grp * 4 + i)];
            phi += ((h >> i) & 1) ? 0.5f * tz : -0.5f * tz;
        }
        float s, c;
        sincosf(phi, &s, &c);
        dC.Pcs[p][h] = make_float2(c, s);
    }
}

// ---------------- helpers ----------------
__device__ __forceinline__ u64 fma2(u64 a, u64 b, u64 c) {
    u64 d; asm("fma.rn.f32x2 %0, %1, %2, %3;" : "=l"(d) : "l"(a), "l"(b), "l"(c));
    return d;
}
__device__ __forceinline__ u64 pk(float lo, float hi) {
    u64 d; asm("mov.b64 %0, {%1, %2};" : "=l"(d) : "f"(lo), "f"(hi));
    return d;
}
__device__ __forceinline__ void upk(u64 v, float& lo, float& hi) {
    asm("mov.b64 {%0, %1}, %2;" : "=f"(lo), "=f"(hi) : "l"(v));
}
__device__ __forceinline__ u64 splat_sgn(float v, u32 sb) {
    u32 b = __float_as_uint(v) ^ sb;
    return ((u64)b << 32) | (u64)b;
}

__device__ __forceinline__ int expand4(int p, const int* bp)
{
    #pragma unroll
    for (int i = 0; i < 4; ++i) {
        int m = (1 << bp[i]) - 1;
        p = ((p & ~m) << 1) | (p & m);
    }
    return p;
}
__device__ __forceinline__ int expand2(int p, const int* bp)
{
    #pragma unroll
    for (int i = 0; i < 2; ++i) {
        int m = (1 << bp[i]) - 1;
        p = ((p & ~m) << 1) | (p & m);
    }
    return p;
}

// ---------------- main kernel ----------------
__global__ __launch_bounds__(NTHREADS, 1)
void qnn_kernel(const float* __restrict__ x, float* __restrict__ out)
{
    extern __shared__ u64 sAmp[];                  // [QDIM] packed (re,im)

    __shared__ Consts sC;
    __shared__ float2 repT[2][8][16];              // lane-replicated phase tables
    __shared__ float cq[NQ], sq[NQ];
    __shared__ float tabLo[128], tabHi[128];
    __shared__ float redbuf[NTHREADS / 32];

    const int tid    = threadIdx.x;
    const int lane16 = tid & 15;
    const int b      = blockIdx.x;

    {   // copy constants to smem
        const int n = (int)(sizeof(Consts) / 4);
        const int* src = (const int*)&dC;
        int* dst = (int*)&sC;
        for (int i = tid; i < n; i += NTHREADS) dst[i] = src[i];
    }

    if (tid < NQ) {
        float ang = x[b * NQ + tid] * 1.57079632679489662f;
        float s, c;
        sincosf(ang, &s, &c);
        cq[tid] = c;
        sq[tid] = s;
    }
    __syncthreads();

    // product-state tables (initial RY layer on |0...0>)
    if (tid < 128) {
        float p = 1.0f;
        #pragma unroll
        for (int k = 0; k < 7; ++k)
            p *= ((tid >> k) & 1) ? sq[NQ - 1 - k] : cq[NQ - 1 - k];
        tabLo[tid] = p;
    } else if (tid < 256) {
        int m = tid - 128;
        float p = 1.0f;
        #pragma unroll
        for (int k = 0; k < 7; ++k)
            p *= ((m >> k) & 1) ? sq[6 - k] : cq[6 - k];
        tabHi[m] = p;
    } else if (tid < 384) {
        int e = (tid - 256) >> 4, l = tid & 15;    // prefill phase table pass 0
        repT[0][e][l] = sC.Pcs[0][e];
    }
    __syncthreads();

    #pragma unroll
    for (int k = 0; k < QDIM / NTHREADS; ++k) {
        int j = tid + k * NTHREADS;
        sAmp[j] = (u64)__float_as_uint(tabHi[j >> 7] * tabLo[j & 127]);
    }

    // ---- 32 passes (per layer: 4,4,4 then 2 gates) ----
    for (int p = 0; p < NPASSES; ++p) {
        __syncthreads();
        const int pb = p & 1;

        // fill next pass's replicated phase table (double-buffered)
        if (tid < 128 && p + 1 < NPASSES) {
            int e = tid >> 4, l = tid & 15;
            repT[pb ^ 1][e][l] = sC.Pcs[p + 1][e];
        }

        if ((p & 3) != 3) {
            // ======== 4-gate pass: one 16-amp coset per thread ========
            int mk[4];
            #pragma unroll
            for (int i = 0; i < 4; ++i) mk[i] = sC.V[p][1 << i];

            int jb = expand4(tid, sC.piv[p]);
            jb ^= sC.fixTab[p][(tid >> sC.fixShift[p]) & 15];

            int bb = 0;
            #pragma unroll
            for (int g = 0; g < 4; ++g)
                bb |= (__popc(sC.F[p][g] & jb) & 1) << g;

            // Gray-order load + scalar phase multiply  a *= (c + i s)
            u64 A[16];
            {
                int j = jb;
                #pragma unroll
                for (int s = 0; s < 16; ++s) {
                    const int g = s ^ (s >> 1);
                    u64 a = sAmp[j];
                    const int h   = g ^ bb;
                    const int m8  = (h << 28) >> 31;          // all-ones if bit3
                    const int idx = h ^ (m8 & 15);
                    float2 z = repT[pb][idx][lane16];
                    float ps = __int_as_float(__float_as_int(z.y) ^ (m8 & 0x80000000));
                    float re, im;
                    upk(a, re, im);
                    float nr = z.x * re - ps * im;
                    float ni = z.x * im + ps * re;
                    A[g] = pk(nr, ni);
                    if (s < 15) {
                        const int c = ((s + 1) & 1) ? 0 : (((s + 1) & 2) ? 1 : (((s + 1) & 4) ? 2 : 3));
                        j ^= mk[c];
                    }
                }
            }

            // 4 RY gates as 3-shear butterflies
            #pragma unroll
            for (int i = 0; i < 4; ++i) {
                const u32 sg   = ((u32)((bb >> i) & 1)) << 31;
                const u64 tnv  = splat_sgn(sC.tq[p][i], sg ^ 0x80000000u);  // -t (role-signed)
                const u64 sv   = splat_sgn(sC.sy[p][i], sg);                //  s (role-signed)

                #pragma unroll
                for (int t = 0; t < 16; ++t) {
                    if (t & (1 << i)) continue;
                    const int t1 = t | (1 << i);
                    u64 Av = A[t], Bv = A[t1];
                    Av = fma2(Bv, tnv, Av);     // x1 = A - t*B
                    Bv = fma2(Av, sv,  Bv);     // y1 = B + s*x1
                    Av = fma2(Bv, tnv, Av);     // x2 = x1 - t*y1
                    A[t] = Av; A[t1] = Bv;
                }
            }

            // Gray-order store
            {
                int j = jb;
                #pragma unroll
                for (int s = 0; s < 16; ++s) {
                    const int g = s ^ (s >> 1);
                    sAmp[j] = A[g];
                    if (s < 15) {
                        const int c = ((s + 1) & 1) ? 0 : (((s + 1) & 2) ? 1 : (((s + 1) & 4) ? 2 : 3));
                        j ^= mk[c];
                    }
                }
            }
        } else {
            // ======== 2-gate pass: four 4-amp cosets per thread ========
            const int m0 = sC.V[p][1], m1 = sC.V[p][2], m01 = sC.V[p][3];
            const int f0 = sC.F[p][0], f1 = sC.F[p][1];
            const int fsh = sC.fixShift[p];
            const float tq0 = sC.tq[p][0], sy0 = sC.sy[p][0];
            const float tq1 = sC.tq[p][1], sy1 = sC.sy[p][1];

            #pragma unroll
            for (int kk = 0; kk < 4; ++kk) {
                const int pp = tid + kk * NTHREADS;
                int jb = expand2(pp, sC.piv[p]);
                jb ^= sC.fixTab[p][(pp >> fsh) & 15];

                const int b0 = __popc(f0 & jb) & 1;
                const int b1 = __popc(f1 & jb) & 1;
                const int bb = b0 | (b1 << 1);

                const int j0 = jb, j1 = jb ^ m0, j2 = jb ^ m1, j3 = jb ^ m01;
                u64 a[4] = { sAmp[j0], sAmp[j1], sAmp[j2], sAmp[j3] };

                #pragma unroll
                for (int g = 0; g < 4; ++g) {
                    float2 z = repT[pb][g ^ bb][lane16];
                    float re, im;
                    upk(a[g], re, im);
                    float nr = z.x * re - z.y * im;
                    float ni = z.x * im + z.y * re;
                    a[g] = pk(nr, ni);
                }

                {   // gate 0: pairs (0,1),(2,3)
                    const u32 sg  = ((u32)b0) << 31;
                    const u64 tnv = splat_sgn(tq0, sg ^ 0x80000000u);
                    const u64 sv  = splat_sgn(sy0, sg);
                    a[0] = fma2(a[1], tnv, a[0]); a[1] = fma2(a[0], sv, a[1]); a[0] = fma2(a[1], tnv, a[0]);
                    a[2] = fma2(a[3], tnv, a[2]); a[3] = fma2(a[2], sv, a[3]); a[2] = fma2(a[3], tnv, a[2]);
                }
                {   // gate 1: pairs (0,2),(1,3)
                    const u32 sg  = ((u32)b1) << 31;
                    const u64 tnv = splat_sgn(tq1, sg ^ 0x80000000u);
                    const u64 sv  = splat_sgn(sy1, sg);
                    a[0] = fma2(a[2], tnv, a[0]); a[2] = fma2(a[0], sv, a[2]); a[0] = fma2(a[2], tnv, a[0]);
                    a[1] = fma2(a[3], tnv, a[1]); a[3] = fma2(a[1], sv, a[3]); a[1] = fma2(a[3], tnv, a[1]);
                }

                sAmp[j0] = a[0]; sAmp[j1] = a[1]; sAmp[j2] = a[2]; sAmp[j3] = a[3];
            }
        }
    }
    __syncthreads();

    // ---- expectation value ----
    const int ff = sC.ffin;
    const float2* sF2 = (const float2*)sAmp;
    float acc = 0.0f;
    #pragma unroll
    for (int k = 0; k < QDIM / NTHREADS; ++k) {
        int j = tid + k * NTHREADS;
        float2 a = sF2[j];
        float pr = a.x * a.x + a.y * a.y;
        acc += (__popc(ff & j) & 1) ? -pr : pr;
    }
    #pragma unroll
    for (int off = 16; off > 0; off >>= 1)
        acc += __shfl_down_sync(0xffffffffu, acc, off);
    if ((tid & 31) == 0) redbuf[tid >> 5] = acc;
    __syncthreads();
    if (tid < 32) {
        float t = redbuf[tid];
        #pragma unroll
        for (int off = 16; off > 0; off >>= 1)
            t += __shfl_down_sync(0xffffffffu, t, off);
        if (tid == 0) out[b] = (t + 1.0f) * 0.5f;
    }
}

extern "C" void kernel_launch(void* const* d_in, const int* in_sizes, int n_in,
                              void* d_out, int out_size)
{
    const float* x      = (const float*)d_in[0];   // (2048, 14)
    const float* params = (const float*)d_in[1];   // (224,)
    float* out          = (float*)d_out;           // (2048,)
    (void)in_sizes; (void)n_in;

    qnn_setup<<<1, 512>>>(params);

    const size_t shmem = (size_t)QDIM * sizeof(u64);   // 128 KB
    cudaFuncSetAttribute(qnn_kernel,
                         cudaFuncAttributeMaxDynamicSharedMemorySize,
                         (int)shmem);
    qnn_kernel<<<out_size, NTHREADS, shmem>>>(x, out);
}